// round 6
// baseline (speedup 1.0000x reference)
#include <cuda_runtime.h>
#include <cuda_fp16.h>
#include <cstdint>

#define B_    16
#define T_    8
#define KBANK 64
#define COUT  128
#define CIN   128
#define HH    64
#define WW    64
#define HP    68
#define WP    68
#define PPW   (COUT * CIN * 25)        // 409600

// ---------------- device scratch (allocation-free) ----------------
__device__ float g_lp[(size_t)B_ * PPW];                       // fp32 [b][o][c][tap]
__device__ unsigned g_Ah[(size_t)B_ * 25 * COUT * (CIN / 2)];  // half2 [b][tap][o][cpair]
__device__ unsigned g_xph[(size_t)B_ * (CIN / 2) * HP * WP];   // half2 [b][cpair][hp][wp]

// ---------------- PTX helpers ----------------
__device__ __forceinline__ uint32_t smem_u32(const void* p) {
    uint32_t a;
    asm("{ .reg .u64 t; cvta.to.shared.u64 t, %1; cvt.u32.u64 %0, t; }" : "=r"(a) : "l"(p));
    return a;
}
#define CP16(smem, gmem) \
    asm volatile("cp.async.cg.shared.global [%0], [%1], 16;" :: "r"(smem), "l"(gmem))
#define CP_COMMIT() asm volatile("cp.async.commit_group;" ::: "memory")
#define CP_WAIT0()  asm volatile("cp.async.wait_group 0;" ::: "memory")

#define MMA16816(c, a, b0v, b1v) \
    asm volatile("mma.sync.aligned.m16n8k16.row.col.f32.f16.f16.f32 " \
        "{%0,%1,%2,%3}, {%4,%5,%6,%7}, {%8,%9}, {%0,%1,%2,%3};" \
        : "+f"((c)[0]), "+f"((c)[1]), "+f"((c)[2]), "+f"((c)[3]) \
        : "r"((a)[0]), "r"((a)[1]), "r"((a)[2]), "r"((a)[3]), "r"(b0v), "r"(b1v))

#define LDMX4(r, addr) \
    asm volatile("ldmatrix.sync.aligned.m8n8.x4.shared.b16 {%0,%1,%2,%3}, [%4];" \
        : "=r"((r)[0]), "=r"((r)[1]), "=r"((r)[2]), "=r"((r)[3]) : "r"(addr))

// ---------------------------------------------------------------------------
// K1: fused coeff + lp:  g_lp[b][p] = sum_k (mean_t tf[b,t,k]) * W[k][p]
// ---------------------------------------------------------------------------
__global__ __launch_bounds__(256) void lp_kernel(const float* __restrict__ W,
                                                 const float* __restrict__ tf) {
    __shared__ float sc[B_ * KBANK];
    int tid = threadIdx.x;
    for (int i = tid; i < B_ * KBANK; i += 256) {
        int b = i >> 6, k = i & 63;
        float s = 0.f;
#pragma unroll
        for (int t = 0; t < T_; t++) s += tf[(b * T_ + t) * KBANK + k];
        sc[i] = s * (1.0f / (float)T_);
    }
    __syncthreads();
    size_t p = (size_t)blockIdx.x * 256 + tid;
    float acc[B_];
#pragma unroll
    for (int b = 0; b < B_; b++) acc[b] = 0.f;
    for (int k = 0; k < KBANK; k++) {
        float wv = W[(size_t)k * PPW + p];
#pragma unroll
        for (int b = 0; b < B_; b++) acc[b] = fmaf(sc[b * KBANK + k], wv, acc[b]);
    }
#pragma unroll
    for (int b = 0; b < B_; b++) g_lp[(size_t)b * PPW + p] = acc[b];
}

// ---------------------------------------------------------------------------
// K2: g_Ah[b][tap][o][cp] = half2(lp[b][o][2cp][tap], lp[b][o][2cp+1][tap])
// ---------------------------------------------------------------------------
__global__ __launch_bounds__(64) void atrans_kernel() {
    int o = blockIdx.x, b = blockIdx.y, cp = threadIdx.x;
    const float* src = g_lp + (((size_t)b * COUT + o) * CIN + 2 * cp) * 25;
    unsigned* dst = g_Ah + ((size_t)b * 25 * COUT + o) * 64 + cp;
#pragma unroll 5
    for (int ij = 0; ij < 25; ij++) {
        __half2 h = __floats2half2_rn(src[ij], src[25 + ij]);
        dst[(size_t)ij * COUT * 64] = *(unsigned*)&h;
    }
}

// ---------------------------------------------------------------------------
// K3: g_xph[b][cp][hp][wp] = half2(x[b][2cp][h][w], x[b][2cp+1][h][w]), pad 0
// grid (cp=64, b=16), 256 thr; coalesced both sides
// ---------------------------------------------------------------------------
__global__ __launch_bounds__(256) void xpad_kernel(const float* __restrict__ x) {
    const int cp = blockIdx.x, b = blockIdx.y;
    const float* x0 = x + ((size_t)(b * CIN + 2 * cp) * HH) * WW;
    const float* x1 = x0 + HH * WW;
    unsigned* dst = g_xph + ((size_t)(b * 64 + cp) * HP) * WP;
    for (int i = threadIdx.x; i < HP * WP; i += 256) {
        int hp = i / WP, wp = i - hp * WP;
        int h = hp - 2, w = wp - 2;
        float v0 = 0.f, v1 = 0.f;
        if ((unsigned)h < HH && (unsigned)w < WW) {
            v0 = x0[h * WW + w];
            v1 = x1[h * WW + w];
        }
        __half2 hh = __floats2half2_rn(v0, v1);
        dst[i] = *(unsigned*)&hh;
    }
}

// ---------------------------------------------------------------------------
// K4: conv as 25 tap-GEMMs, mma m16n8k16 fp16/fp32.
// CTA = (b, 4 rows): D[128 cout, 256 px]. 512 thr, 16 warps = 2M x 8N,
// warp tile 64 cout x 32 px (4 m16 x 4 n8).
// cin chunks of 32 (16 cp). A: 5-tap groups, 80B-pitch rows (ldmatrix,
// conflict-free un-swizzled), double-buffered. B halo [16cp][8 rows x 68].
// ---------------------------------------------------------------------------
#define AP    20                       // A pitch in words (80 B)
#define AG    (5 * 128 * AP)           // words per 5-tap A group = 12800
#define SA0   0
#define SA1   AG
#define SBOFF (2 * AG)                 // 25600
#define BP    552
#define SMW   (SBOFF + 16 * BP)        // 34432 words = 137728 B

__device__ __forceinline__ void stage_a_grp(uint32_t sb, const unsigned* Abase,
                                            int cc, int grp, int buf) {
    // 5 taps x 128 couts x 4 float4 = 2560 CP16; 5 per thread
    const uint32_t dbase = sb + (buf ? SA1 : SA0) * 4;
#pragma unroll
    for (int i = 0; i < 5; i++) {
        int idx = threadIdx.x + (i << 9);
        int tl = idx >> 9;             // == i
        int rem = idx & 511;
        int o = rem >> 2, f = rem & 3;
        const unsigned* src = Abase + ((size_t)(grp * 5 + tl) * COUT + o) * 64
                                    + cc * 16 + f * 4;
        CP16(dbase + (uint32_t)(tl * 2560 + o * AP + f * 4) * 4, src);
    }
}

__global__ __launch_bounds__(512, 1) void conv_kernel(float* __restrict__ out) {
    extern __shared__ uint32_t sm[];
    const uint32_t sb = smem_u32(sm);
    const int tid = threadIdx.x;
    const int lane = tid & 31;
    const int wid = tid >> 5;
    const int g = lane >> 2, t = lane & 3;
    const int wm = wid & 1;            // 2 M-warps (64 couts each)
    const int wn = wid >> 1;           // 8 N-warps (32 px each)
    const int orow = wn >> 1;          // output row within CTA tile (0..3)
    const int w0 = (wn & 1) * 32;      // col offset
    const int b = blockIdx.y, h0 = blockIdx.x * 4;

    const unsigned* Abase = g_Ah + (size_t)b * 25 * COUT * 64;
    const unsigned* Xbase = g_xph + (size_t)b * 64 * HP * WP;

    // per-lane ldmatrix base (row = wm*64 + lane&15, col-chunk = lane>>4)
    const uint32_t a_lane = (uint32_t)((wm * 64 + (lane & 15)) * AP + (lane >> 4) * 4) * 4;

    float acc[4][4][4];
#pragma unroll
    for (int mt = 0; mt < 4; mt++)
#pragma unroll
        for (int nt = 0; nt < 4; nt++)
#pragma unroll
            for (int q = 0; q < 4; q++) acc[mt][nt][q] = 0.f;

    for (int cc = 0; cc < 4; cc++) {
        // ---- stage B halo: 16 cp x 8 padded rows x 68 ----
        for (int idx = tid; idx < 2176; idx += 512) {
            int cp = idx / 136, rem = idx - cp * 136;
            int r = rem / 17, f = rem - r * 17;
            const unsigned* src = Xbase + (size_t)(cc * 16 + cp) * HP * WP
                                        + (h0 + r) * WP + f * 4;
            CP16(sb + (uint32_t)(SBOFF + cp * BP + r * WP + f * 4) * 4, src);
        }
        stage_a_grp(sb, Abase, cc, 0, 0);
        CP_COMMIT(); CP_WAIT0(); __syncthreads();

        for (int grp = 0; grp < 5; grp++) {
            const int buf = grp & 1;
            if (grp < 4) { stage_a_grp(sb, Abase, cc, grp + 1, buf ^ 1); CP_COMMIT(); }

            const uint32_t abuf = sb + (buf ? SA1 : SA0) * 4 + a_lane;
#pragma unroll
            for (int tl = 0; tl < 5; tl++) {
                const int tap = grp * 5 + tl;
                const int di = tap / 5, dj = tap % 5;
                const uint32_t atap = abuf + (uint32_t)(tl * 2560) * 4;
                const uint32_t* sB = sm + SBOFF;
                const int pixbase = (orow + di) * WP + dj + w0 + g;

#pragma unroll
                for (int kk = 0; kk < 2; kk++) {
                    uint32_t a[4][4];
#pragma unroll
                    for (int mt = 0; mt < 4; mt++)
                        LDMX4(a[mt], atap + (uint32_t)(mt * 16 * AP + kk * 8) * 4);
                    const uint32_t* bp0 = sB + (kk * 8 + t) * BP + pixbase;
                    const uint32_t* bp1 = bp0 + 4 * BP;
#pragma unroll
                    for (int nt = 0; nt < 4; nt++) {
                        uint32_t b0 = bp0[nt * 8], b1 = bp1[nt * 8];
#pragma unroll
                        for (int mt = 0; mt < 4; mt++)
                            MMA16816(acc[mt][nt], a[mt], b0, b1);
                    }
                }
            }
            CP_WAIT0(); __syncthreads();
        }
    }

    // ---- epilogue ----
    const int h = h0 + orow;
#pragma unroll
    for (int mt = 0; mt < 4; mt++) {
#pragma unroll
        for (int rr = 0; rr < 2; rr++) {
            int cout = wm * 64 + mt * 16 + g + rr * 8;
            float* op = out + (((size_t)b * COUT + cout) * HH + h) * WW + w0;
#pragma unroll
            for (int nt = 0; nt < 4; nt++) {
                float2 v = make_float2(acc[mt][nt][rr * 2], acc[mt][nt][rr * 2 + 1]);
                *(float2*)(op + nt * 8 + 2 * t) = v;
            }
        }
    }
}

// ---------------------------------------------------------------------------
extern "C" void kernel_launch(void* const* d_in, const int* in_sizes, int n_in,
                              void* d_out, int out_size) {
    (void)in_sizes; (void)n_in; (void)out_size;
    const float* x  = (const float*)d_in[0];   // (16,128,64,64)
    const float* tf = (const float*)d_in[1];   // (16,8,64)
    const float* W  = (const float*)d_in[2];   // (64,128,128,5,5)
    float* out = (float*)d_out;                // (16,128,64,64)

    cudaFuncSetAttribute(conv_kernel, cudaFuncAttributeMaxDynamicSharedMemorySize,
                         SMW * 4);

    lp_kernel<<<PPW / 256, 256>>>(W, tf);
    atrans_kernel<<<dim3(COUT, B_), 64>>>();
    xpad_kernel<<<dim3(64, B_), 256>>>(x);
    conv_kernel<<<dim3(HH / 4, B_), 512, SMW * 4>>>(out);
}

// round 7
// speedup vs baseline: 1.3102x; 1.3102x over previous
#include <cuda_runtime.h>
#include <cuda_fp16.h>
#include <cstdint>

#define B_    16
#define T_    8
#define KBANK 64
#define COUT  128
#define CIN   128
#define HH    64
#define WW    64
#define HP    68
#define WP    68
#define PPW   (COUT * CIN * 25)        // 409600

// ---------------- device scratch (allocation-free) ----------------
__device__ float g_lp[(size_t)B_ * PPW];                       // fp32 [b][o][c][tap]
__device__ unsigned g_Ah[(size_t)B_ * 25 * COUT * (CIN / 2)];  // half2 [b][tap][o][cpair]
__device__ unsigned g_xph[(size_t)B_ * (CIN / 2) * HP * WP];   // half2 [b][cpair][hp][wp]

// ---------------- PTX helpers ----------------
__device__ __forceinline__ uint32_t smem_u32(const void* p) {
    uint32_t a;
    asm("{ .reg .u64 t; cvta.to.shared.u64 t, %1; cvt.u32.u64 %0, t; }" : "=r"(a) : "l"(p));
    return a;
}
#define CP16(smem, gmem) \
    asm volatile("cp.async.cg.shared.global [%0], [%1], 16;" :: "r"(smem), "l"(gmem))
#define CP_COMMIT() asm volatile("cp.async.commit_group;" ::: "memory")
#define CP_WAIT0()  asm volatile("cp.async.wait_group 0;" ::: "memory")

#define MMA16816(c, a, b0v, b1v) \
    asm volatile("mma.sync.aligned.m16n8k16.row.col.f32.f16.f16.f32 " \
        "{%0,%1,%2,%3}, {%4,%5,%6,%7}, {%8,%9}, {%0,%1,%2,%3};" \
        : "+f"((c)[0]), "+f"((c)[1]), "+f"((c)[2]), "+f"((c)[3]) \
        : "r"((a)[0]), "r"((a)[1]), "r"((a)[2]), "r"((a)[3]), "r"(b0v), "r"(b1v))

// ---------------------------------------------------------------------------
// K1: fused coeff + lp:  g_lp[b][p] = sum_k (mean_t tf[b,t,k]) * W[k][p]
// ---------------------------------------------------------------------------
__global__ __launch_bounds__(256) void lp_kernel(const float* __restrict__ W,
                                                 const float* __restrict__ tf) {
    __shared__ float sc[B_ * KBANK];
    int tid = threadIdx.x;
    for (int i = tid; i < B_ * KBANK; i += 256) {
        int b = i >> 6, k = i & 63;
        float s = 0.f;
#pragma unroll
        for (int t = 0; t < T_; t++) s += tf[(b * T_ + t) * KBANK + k];
        sc[i] = s * (1.0f / (float)T_);
    }
    __syncthreads();
    size_t p = (size_t)blockIdx.x * 256 + tid;
    float acc[B_];
#pragma unroll
    for (int b = 0; b < B_; b++) acc[b] = 0.f;
    for (int k = 0; k < KBANK; k++) {
        float wv = W[(size_t)k * PPW + p];
#pragma unroll
        for (int b = 0; b < B_; b++) acc[b] = fmaf(sc[b * KBANK + k], wv, acc[b]);
    }
#pragma unroll
    for (int b = 0; b < B_; b++) g_lp[(size_t)b * PPW + p] = acc[b];
}

// ---------------------------------------------------------------------------
// K2: g_Ah[b][tap][o][cp] = half2(lp[b][o][2cp][tap], lp[b][o][2cp+1][tap])
// ---------------------------------------------------------------------------
__global__ __launch_bounds__(64) void atrans_kernel() {
    int o = blockIdx.x, b = blockIdx.y, cp = threadIdx.x;
    const float* src = g_lp + (((size_t)b * COUT + o) * CIN + 2 * cp) * 25;
    unsigned* dst = g_Ah + ((size_t)b * 25 * COUT + o) * 64 + cp;
#pragma unroll 5
    for (int ij = 0; ij < 25; ij++) {
        __half2 h = __floats2half2_rn(src[ij], src[25 + ij]);
        dst[(size_t)ij * COUT * 64] = *(unsigned*)&h;
    }
}

// ---------------------------------------------------------------------------
// K3: g_xph[b][cp][hp][wp] = half2(x[b][2cp][h][w], x[b][2cp+1][h][w]), pad 0
// ---------------------------------------------------------------------------
__global__ __launch_bounds__(256) void xpad_kernel(const float* __restrict__ x) {
    const int cp = blockIdx.x, b = blockIdx.y;
    const float* x0 = x + ((size_t)(b * CIN + 2 * cp) * HH) * WW;
    const float* x1 = x0 + HH * WW;
    unsigned* dst = g_xph + ((size_t)(b * 64 + cp) * HP) * WP;
    for (int i = threadIdx.x; i < HP * WP; i += 256) {
        int hp = i / WP, wp = i - hp * WP;
        int h = hp - 2, w = wp - 2;
        float v0 = 0.f, v1 = 0.f;
        if ((unsigned)h < HH && (unsigned)w < WW) {
            v0 = x0[h * WW + w];
            v1 = x1[h * WW + w];
        }
        __half2 hh = __floats2half2_rn(v0, v1);
        dst[i] = *(unsigned*)&hh;
    }
}

// ---------------------------------------------------------------------------
// K4: conv as 25 tap-GEMMs, mma m16n8k16 fp16/fp32.
// CTA = (b, 2 output rows): D[128 cout, 128 px]. 256 thr, 8 warps = 4M x 2N,
// warp tile 32 cout x 64 px (2 m16 x 8 n8) — R5's proven shape.
// cin chunks of 32 (16 cp): B halo [16 cp][6 rows x 68] pitch 408,
// A [128 o][16 cp] pitch 20, per-tap double-buffered. 46.6 KB smem -> 2 CTA/SM.
// ---------------------------------------------------------------------------
#define AP  20
#define BP  408
#define SA0 0
#define SA1 2560
#define SBOFF 5120
#define SMW (SBOFF + 16 * BP)          // 11648 words = 46592 B

__device__ __forceinline__ void stage_a(uint32_t sb, const unsigned* Abase,
                                        int cc, int tap, int buf) {
    const uint32_t dbase = sb + (buf ? SA1 : SA0) * 4;
#pragma unroll
    for (int i = 0; i < 2; i++) {
        int idx = threadIdx.x + (i << 8);          // < 512
        int o = idx >> 2, f = idx & 3;
        const unsigned* src = Abase + ((size_t)tap * COUT + o) * 64 + cc * 16 + f * 4;
        CP16(dbase + (uint32_t)(o * AP + f * 4) * 4, src);
    }
}

__global__ __launch_bounds__(256, 2) void conv_kernel(float* __restrict__ out) {
    extern __shared__ uint32_t sm[];
    const uint32_t sb = smem_u32(sm);
    const int tid = threadIdx.x;
    const int lane = tid & 31;
    const int wid = tid >> 5;
    const int g = lane >> 2, t = lane & 3;
    const int wm = wid & 3;            // 4 M-warps (32 couts each)
    const int wn = wid >> 2;           // 2 N-warps (one output row each)
    const int b = blockIdx.y, h0 = blockIdx.x * 2;

    const unsigned* Abase = g_Ah + (size_t)b * 25 * COUT * 64;
    const unsigned* Xbase = g_xph + (size_t)b * 64 * HP * WP;

    float acc[2][8][4];
#pragma unroll
    for (int mt = 0; mt < 2; mt++)
#pragma unroll
        for (int nt = 0; nt < 8; nt++)
#pragma unroll
            for (int q = 0; q < 4; q++) acc[mt][nt][q] = 0.f;

    for (int cc = 0; cc < 4; cc++) {
        // ---- stage B halo: 16 cp x 6 padded rows x 68 cols ----
        for (int idx = tid; idx < 1632; idx += 256) {
            int cp = idx / 102, rem = idx - cp * 102;
            int r = rem / 17, f = rem - r * 17;
            const unsigned* src = Xbase + (size_t)(cc * 16 + cp) * HP * WP
                                        + (h0 + r) * WP + f * 4;
            CP16(sb + (uint32_t)(SBOFF + cp * BP + r * WP + f * 4) * 4, src);
        }
        stage_a(sb, Abase, cc, 0, 0);
        CP_COMMIT(); CP_WAIT0(); __syncthreads();

        for (int tap = 0; tap < 25; tap++) {
            const int buf = tap & 1;
            if (tap + 1 < 25) { stage_a(sb, Abase, cc, tap + 1, buf ^ 1); CP_COMMIT(); }
            const int di = tap / 5, dj = tap % 5;
            const uint32_t* sA = sm + (buf ? SA1 : SA0);
            const uint32_t* sB = sm + SBOFF;
            const int pixbase = (wn + di) * WP + dj + g;

#pragma unroll
            for (int kk = 0; kk < 2; kk++) {
                uint32_t a[2][4];
#pragma unroll
                for (int mt = 0; mt < 2; mt++) {
                    const uint32_t* ap = sA + (wm * 32 + mt * 16 + g) * AP
                                            + kk * 8 + t;
                    a[mt][0] = ap[0];            // row g,   cpair t
                    a[mt][1] = ap[8 * AP];       // row g+8, cpair t
                    a[mt][2] = ap[4];            // row g,   cpair t+4
                    a[mt][3] = ap[8 * AP + 4];   // row g+8, cpair t+4
                }
                const uint32_t* bp0 = sB + (kk * 8 + t) * BP + pixbase;
                const uint32_t* bp1 = bp0 + 4 * BP;
#pragma unroll
                for (int nt = 0; nt < 8; nt++) {
                    uint32_t b0 = bp0[nt * 8], b1 = bp1[nt * 8];
                    MMA16816(acc[0][nt], a[0], b0, b1);
                    MMA16816(acc[1][nt], a[1], b0, b1);
                }
            }
            CP_WAIT0(); __syncthreads();
        }
    }

    // ---- epilogue ----
    const int h = h0 + wn;
#pragma unroll
    for (int mt = 0; mt < 2; mt++) {
#pragma unroll
        for (int rr = 0; rr < 2; rr++) {
            int cout = wm * 32 + mt * 16 + g + rr * 8;
            float* op = out + (((size_t)b * COUT + cout) * HH + h) * WW;
#pragma unroll
            for (int nt = 0; nt < 8; nt++) {
                float2 v = make_float2(acc[mt][nt][rr * 2], acc[mt][nt][rr * 2 + 1]);
                *(float2*)(op + nt * 8 + 2 * t) = v;
            }
        }
    }
}

// ---------------------------------------------------------------------------
extern "C" void kernel_launch(void* const* d_in, const int* in_sizes, int n_in,
                              void* d_out, int out_size) {
    (void)in_sizes; (void)n_in; (void)out_size;
    const float* x  = (const float*)d_in[0];   // (16,128,64,64)
    const float* tf = (const float*)d_in[1];   // (16,8,64)
    const float* W  = (const float*)d_in[2];   // (64,128,128,5,5)
    float* out = (float*)d_out;                // (16,128,64,64)

    cudaFuncSetAttribute(conv_kernel, cudaFuncAttributeMaxDynamicSharedMemorySize,
                         SMW * 4);

    lp_kernel<<<PPW / 256, 256>>>(W, tf);
    atrans_kernel<<<dim3(COUT, B_), 64>>>();
    xpad_kernel<<<dim3(64, B_), 256>>>(x);
    conv_kernel<<<dim3(HH / 2, B_), 256, SMW * 4>>>(out);
}